// round 2
// baseline (speedup 1.0000x reference)
#include <cuda_runtime.h>

#define SQ 4096      // sequence length S
#define ND 1024      // model dim N
#define FD 4096      // ffn dim 4N

// ---------------- scratch (allocation-free: static device globals) ----------
__device__ float g_xn[(size_t)SQ * ND];   // 16 MB
__device__ float g_q [(size_t)SQ * ND];
__device__ float g_k [(size_t)SQ * ND];
__device__ float g_v [(size_t)SQ * ND];
__device__ float g_s [(size_t)SQ * SQ];   // 64 MB scores / probs
__device__ float g_h [(size_t)SQ * ND];
__device__ float g_m [(size_t)SQ * FD];   // 64 MB ffn mid

// ---------------- reductions ----------------
__device__ __forceinline__ float warpSum(float v) {
    #pragma unroll
    for (int o = 16; o; o >>= 1) v += __shfl_xor_sync(0xffffffffu, v, o);
    return v;
}
__device__ __forceinline__ float warpMax(float v) {
    #pragma unroll
    for (int o = 16; o; o >>= 1) v = fmaxf(v, __shfl_xor_sync(0xffffffffu, v, o));
    return v;
}

// ---------------- LayerNorm: one block per row (256 thr, 4 elem/thr) --------
__global__ __launch_bounds__(256) void ln_kernel(const float* __restrict__ x,
                          const float* __restrict__ g,
                          const float* __restrict__ b) {
    int row = blockIdx.x;
    int t = threadIdx.x;
    const float4* xr = (const float4*)(x + (size_t)row * ND);
    float4 xv = xr[t];
    float s1 = xv.x + xv.y + xv.z + xv.w;
    float s2 = xv.x*xv.x + xv.y*xv.y + xv.z*xv.z + xv.w*xv.w;

    __shared__ float shA[8], shB[8];
    s1 = warpSum(s1); s2 = warpSum(s2);
    if ((t & 31) == 0) { shA[t >> 5] = s1; shB[t >> 5] = s2; }
    __syncthreads();
    if (t < 32) {
        float a = (t < 8) ? shA[t] : 0.0f;
        float c = (t < 8) ? shB[t] : 0.0f;
        a = warpSum(a); c = warpSum(c);
        if (t == 0) { shA[0] = a; shB[0] = c; }
    }
    __syncthreads();
    float mu  = shA[0] * (1.0f / ND);
    float var = shB[0] * (1.0f / ND) - mu * mu;
    float rstd = rsqrtf(var + 1e-5f);

    float4 gv = ((const float4*)g)[t];
    float4 bv = ((const float4*)b)[t];
    float4 o;
    o.x = (xv.x - mu) * rstd * gv.x + bv.x;
    o.y = (xv.y - mu) * rstd * gv.y + bv.y;
    o.z = (xv.z - mu) * rstd * gv.z + bv.z;
    o.w = (xv.w - mu) * rstd * gv.w + bv.w;
    ((float4*)(g_xn + (size_t)row * ND))[t] = o;
}

// ---------------- Softmax over rows of length SQ (256 thr, 16 elem/thr) -----
__global__ __launch_bounds__(256) void softmax_kernel() {
    int row = blockIdx.x;
    int t = threadIdx.x;
    float4* r = (float4*)(g_s + (size_t)row * SQ);
    float4 v[4];
    float mx = -1e30f;
    #pragma unroll
    for (int i = 0; i < 4; i++) {
        v[i] = r[t + i * 256];
        mx = fmaxf(mx, fmaxf(fmaxf(v[i].x, v[i].y), fmaxf(v[i].z, v[i].w)));
    }
    __shared__ float shA[8], shB[8];
    mx = warpMax(mx);
    if ((t & 31) == 0) shA[t >> 5] = mx;
    __syncthreads();
    if (t < 32) {
        float a = (t < 8) ? shA[t] : -1e30f;
        a = warpMax(a);
        if (t == 0) shA[0] = a;
    }
    __syncthreads();
    mx = shA[0];

    float sum = 0.0f;
    #pragma unroll
    for (int i = 0; i < 4; i++) {
        v[i].x = __expf(v[i].x - mx);
        v[i].y = __expf(v[i].y - mx);
        v[i].z = __expf(v[i].z - mx);
        v[i].w = __expf(v[i].w - mx);
        sum += v[i].x + v[i].y + v[i].z + v[i].w;
    }
    sum = warpSum(sum);
    if ((t & 31) == 0) shB[t >> 5] = sum;
    __syncthreads();
    if (t < 32) {
        float a = (t < 8) ? shB[t] : 0.0f;
        a = warpSum(a);
        if (t == 0) shB[0] = a;
    }
    __syncthreads();
    float inv = 1.0f / shB[0];
    #pragma unroll
    for (int i = 0; i < 4; i++) {
        v[i].x *= inv; v[i].y *= inv; v[i].z *= inv; v[i].w *= inv;
        r[t + i * 256] = v[i];
    }
}

// ---------------- SGEMM: C = act(scale * (A@B) + bias) (+ resid) ------------
// A: [M,K] row-major.
// BT=false: B [K,Nn] row-major. BT=true: B [Nn,K] row-major (C=A@B^T).
// ACT=1: LeakyReLU(0.1). RES=true: add resid[M,Nn].
// Tiles: 128x128x16, 256 threads, 8x8 per thread.
template<bool BT, int ACT, bool RES>
__global__ __launch_bounds__(256) void sgemm_kernel(
    const float* __restrict__ A, const float* __restrict__ B,
    const float* __restrict__ bias, const float* __restrict__ resid,
    float* __restrict__ C, int M, int Nn, int K, float scale)
{
    __shared__ float As[16][132];
    __shared__ float Bs[16][132];

    int tid = threadIdx.x;
    int bm = blockIdx.y * 128;
    int bn = blockIdx.x * 128;
    int tx = tid & 15;        // 0..15 -> 8 cols each
    int ty = tid >> 4;        // 0..15 -> 8 rows each

    float acc[8][8];
    #pragma unroll
    for (int i = 0; i < 8; i++)
        #pragma unroll
        for (int j = 0; j < 8; j++) acc[i][j] = 0.0f;

    for (int k0 = 0; k0 < K; k0 += 16) {
        // load A tile 128x16 (transposed into As[k][m])
        #pragma unroll
        for (int it = 0; it < 2; it++) {
            int idx = tid + it * 256;      // 0..511
            int r = idx >> 2;              // row within tile 0..127
            int c = (idx & 3) << 2;        // k offset 0,4,8,12
            float4 va = *(const float4*)(A + (size_t)(bm + r) * K + k0 + c);
            As[c + 0][r] = va.x; As[c + 1][r] = va.y;
            As[c + 2][r] = va.z; As[c + 3][r] = va.w;
        }
        if (BT) {
            // B tile: rows = output cols, 128x16, transposed into Bs[k][n]
            #pragma unroll
            for (int it = 0; it < 2; it++) {
                int idx = tid + it * 256;
                int r = idx >> 2;
                int c = (idx & 3) << 2;
                float4 vb = *(const float4*)(B + (size_t)(bn + r) * K + k0 + c);
                Bs[c + 0][r] = vb.x; Bs[c + 1][r] = vb.y;
                Bs[c + 2][r] = vb.z; Bs[c + 3][r] = vb.w;
            }
        } else {
            // B tile 16x128, direct
            #pragma unroll
            for (int it = 0; it < 2; it++) {
                int idx = tid + it * 256;
                int r = idx >> 5;              // k row 0..15
                int c = (idx & 31) << 2;       // n offset
                float4 vb = *(const float4*)(B + (size_t)(k0 + r) * Nn + bn + c);
                *(float4*)&Bs[r][c] = vb;
            }
        }
        __syncthreads();

        #pragma unroll
        for (int kk = 0; kk < 16; kk++) {
            float a[8], b[8];
            *(float4*)(a)     = *(float4*)&As[kk][ty * 8];
            *(float4*)(a + 4) = *(float4*)&As[kk][ty * 8 + 4];
            *(float4*)(b)     = *(float4*)&Bs[kk][tx * 8];
            *(float4*)(b + 4) = *(float4*)&Bs[kk][tx * 8 + 4];
            #pragma unroll
            for (int i = 0; i < 8; i++)
                #pragma unroll
                for (int j = 0; j < 8; j++)
                    acc[i][j] = fmaf(a[i], b[j], acc[i][j]);
        }
        __syncthreads();
    }

    // epilogue
    float bvals[8];
    #pragma unroll
    for (int j = 0; j < 8; j++)
        bvals[j] = bias ? bias[bn + tx * 8 + j] : 0.0f;

    #pragma unroll
    for (int i = 0; i < 8; i++) {
        size_t off = (size_t)(bm + ty * 8 + i) * Nn + bn + tx * 8;
        #pragma unroll
        for (int j = 0; j < 8; j += 4) {
            float o[4];
            #pragma unroll
            for (int q = 0; q < 4; q++) {
                float val = acc[i][j + q] * scale + bvals[j + q];
                if (ACT == 1) val = (val > 0.0f) ? val : 0.1f * val;
                if (RES) val += resid[off + j + q];
                o[q] = val;
            }
            *(float4*)(C + off + j) = *(float4*)o;
        }
    }
}

// ---------------- host side ----------------
extern "C" void kernel_launch(void* const* d_in, const int* in_sizes, int n_in,
                              void* d_out, int out_size) {
    const float* x      = (const float*)d_in[0];
    const float* norm_g = (const float*)d_in[1];
    const float* norm_b = (const float*)d_in[2];
    const float* Wq = (const float*)d_in[3];
    const float* bq = (const float*)d_in[4];
    const float* Wk = (const float*)d_in[5];
    const float* bk = (const float*)d_in[6];
    const float* Wv = (const float*)d_in[7];
    const float* bv = (const float*)d_in[8];
    const float* W1 = (const float*)d_in[9];
    const float* b1 = (const float*)d_in[10];
    const float* W2 = (const float*)d_in[11];
    const float* b2 = (const float*)d_in[12];
    float* out = (float*)d_out;

    float *xn, *q, *k, *v, *s, *h, *m;
    cudaGetSymbolAddress((void**)&xn, g_xn);
    cudaGetSymbolAddress((void**)&q,  g_q);
    cudaGetSymbolAddress((void**)&k,  g_k);
    cudaGetSymbolAddress((void**)&v,  g_v);
    cudaGetSymbolAddress((void**)&s,  g_s);
    cudaGetSymbolAddress((void**)&h,  g_h);
    cudaGetSymbolAddress((void**)&m,  g_m);

    // 1. LayerNorm  (writes g_xn directly)
    ln_kernel<<<SQ, 256>>>(x, norm_g, norm_b);

    // 2. q/k/v projections: [SQ,ND] @ [ND,ND] + b
    dim3 gNN(ND / 128, SQ / 128);
    sgemm_kernel<false, 0, false><<<gNN, 256>>>(xn, Wq, bq, nullptr, q, SQ, ND, ND, 1.0f);
    sgemm_kernel<false, 0, false><<<gNN, 256>>>(xn, Wk, bk, nullptr, k, SQ, ND, ND, 1.0f);
    sgemm_kernel<false, 0, false><<<gNN, 256>>>(xn, Wv, bv, nullptr, v, SQ, ND, ND, 1.0f);

    // 3. scores = (k @ q^T) / sqrt(N)   -> [SQ, SQ]
    dim3 gSS(SQ / 128, SQ / 128);
    sgemm_kernel<true, 0, false><<<gSS, 256>>>(k, q, nullptr, nullptr, s, SQ, SQ, ND, 0.03125f);

    // 4. softmax rows (in-place on g_s)
    softmax_kernel<<<SQ, 256>>>();

    // 5. h = P @ v   [SQ,SQ] @ [SQ,ND]
    sgemm_kernel<false, 0, false><<<gNN, 256>>>(s, v, nullptr, nullptr, h, SQ, ND, SQ, 1.0f);

    // 6. mid = leaky_relu(h @ W1 + b1)   [SQ,ND] @ [ND,FD]
    dim3 gNF(FD / 128, SQ / 128);
    sgemm_kernel<false, 1, false><<<gNF, 256>>>(h, W1, b1, nullptr, m, SQ, FD, ND, 1.0f);

    // 7. out = mid @ W2 + b2 + xn   [SQ,FD] @ [FD,ND]
    sgemm_kernel<false, 0, true><<<gNN, 256>>>(m, W2, b2, xn, out, SQ, ND, FD, 1.0f);
}

// round 3
// speedup vs baseline: 2.9603x; 2.9603x over previous
#include <cuda_runtime.h>
#include <cstdint>

#define SQ 4096      // sequence length S
#define ND 1024      // model dim N
#define FD 4096      // ffn dim 4N

// ---------------- scratch (allocation-free: static device globals) ----------
__device__ float g_xn[(size_t)SQ * ND];   // 16 MB
__device__ float g_q [(size_t)SQ * ND];
__device__ float g_k [(size_t)SQ * ND];
__device__ float g_v [(size_t)SQ * ND];
__device__ float g_s [(size_t)SQ * SQ];   // 64 MB scores / probs
__device__ float g_h [(size_t)SQ * ND];
__device__ float g_m [(size_t)SQ * FD];   // 64 MB ffn mid

// ---------------- small helpers ----------------
__device__ __forceinline__ float warpSum(float v) {
    #pragma unroll
    for (int o = 16; o; o >>= 1) v += __shfl_xor_sync(0xffffffffu, v, o);
    return v;
}
__device__ __forceinline__ float warpMax(float v) {
    #pragma unroll
    for (int o = 16; o; o >>= 1) v = fmaxf(v, __shfl_xor_sync(0xffffffffu, v, o));
    return v;
}

__device__ __forceinline__ uint32_t f2tf32(float f) {
    uint32_t r;
    asm("cvt.rna.tf32.f32 %0, %1;" : "=r"(r) : "f"(f));
    return r;
}

__device__ __forceinline__ void cp_async16(void* smem_dst, const void* gmem_src) {
    uint32_t s = (uint32_t)__cvta_generic_to_shared(smem_dst);
    asm volatile("cp.async.cg.shared.global [%0], [%1], 16;" :: "r"(s), "l"(gmem_src));
}
__device__ __forceinline__ void cp_commit() {
    asm volatile("cp.async.commit_group;" ::: "memory");
}
template<int NN>
__device__ __forceinline__ void cp_wait() {
    asm volatile("cp.async.wait_group %0;" :: "n"(NN) : "memory");
}

__device__ __forceinline__ void mma_tf32(float* c, const uint32_t* a, const uint32_t* b) {
    asm volatile(
        "mma.sync.aligned.m16n8k8.row.col.f32.tf32.tf32.f32 "
        "{%0,%1,%2,%3}, {%4,%5,%6,%7}, {%8,%9}, {%0,%1,%2,%3};"
        : "+f"(c[0]), "+f"(c[1]), "+f"(c[2]), "+f"(c[3])
        : "r"(a[0]), "r"(a[1]), "r"(a[2]), "r"(a[3]), "r"(b[0]), "r"(b[1]));
}

// ---------------- LayerNorm ----------------
__global__ __launch_bounds__(256) void ln_kernel(const float* __restrict__ x,
                          const float* __restrict__ g,
                          const float* __restrict__ b) {
    int row = blockIdx.x;
    int t = threadIdx.x;
    const float4* xr = (const float4*)(x + (size_t)row * ND);
    float4 xv = xr[t];
    float s1 = xv.x + xv.y + xv.z + xv.w;
    float s2 = xv.x*xv.x + xv.y*xv.y + xv.z*xv.z + xv.w*xv.w;

    __shared__ float shA[8], shB[8];
    s1 = warpSum(s1); s2 = warpSum(s2);
    if ((t & 31) == 0) { shA[t >> 5] = s1; shB[t >> 5] = s2; }
    __syncthreads();
    if (t < 32) {
        float a = (t < 8) ? shA[t] : 0.0f;
        float c = (t < 8) ? shB[t] : 0.0f;
        a = warpSum(a); c = warpSum(c);
        if (t == 0) { shA[0] = a; shB[0] = c; }
    }
    __syncthreads();
    float mu  = shA[0] * (1.0f / ND);
    float var = shB[0] * (1.0f / ND) - mu * mu;
    float rstd = rsqrtf(var + 1e-5f);

    float4 gv = ((const float4*)g)[t];
    float4 bv = ((const float4*)b)[t];
    float4 o;
    o.x = (xv.x - mu) * rstd * gv.x + bv.x;
    o.y = (xv.y - mu) * rstd * gv.y + bv.y;
    o.z = (xv.z - mu) * rstd * gv.z + bv.z;
    o.w = (xv.w - mu) * rstd * gv.w + bv.w;
    ((float4*)(g_xn + (size_t)row * ND))[t] = o;
}

// ---------------- Softmax over rows of length SQ ----------------
__global__ __launch_bounds__(256) void softmax_kernel() {
    int row = blockIdx.x;
    int t = threadIdx.x;
    float4* r = (float4*)(g_s + (size_t)row * SQ);
    float4 v[4];
    float mx = -1e30f;
    #pragma unroll
    for (int i = 0; i < 4; i++) {
        v[i] = r[t + i * 256];
        mx = fmaxf(mx, fmaxf(fmaxf(v[i].x, v[i].y), fmaxf(v[i].z, v[i].w)));
    }
    __shared__ float shA[8], shB[8];
    mx = warpMax(mx);
    if ((t & 31) == 0) shA[t >> 5] = mx;
    __syncthreads();
    if (t < 32) {
        float a = (t < 8) ? shA[t] : -1e30f;
        a = warpMax(a);
        if (t == 0) shA[0] = a;
    }
    __syncthreads();
    mx = shA[0];

    float sum = 0.0f;
    #pragma unroll
    for (int i = 0; i < 4; i++) {
        v[i].x = __expf(v[i].x - mx);
        v[i].y = __expf(v[i].y - mx);
        v[i].z = __expf(v[i].z - mx);
        v[i].w = __expf(v[i].w - mx);
        sum += v[i].x + v[i].y + v[i].z + v[i].w;
    }
    sum = warpSum(sum);
    if ((t & 31) == 0) shB[t >> 5] = sum;
    __syncthreads();
    if (t < 32) {
        float a = (t < 8) ? shB[t] : 0.0f;
        a = warpSum(a);
        if (t == 0) shB[0] = a;
    }
    __syncthreads();
    float inv = 1.0f / shB[0];
    #pragma unroll
    for (int i = 0; i < 4; i++) {
        v[i].x *= inv; v[i].y *= inv; v[i].z *= inv; v[i].w *= inv;
        r[t + i * 256] = v[i];
    }
}

// ---------------- TF32 tensor-core GEMM ----------------
// C[M,Nn] = act(scale * (A @ B) + bias) (+ resid)
// A: [M,K] row-major.
// BT=false: B [K,Nn] row-major.  BT=true: B [Nn,K] row-major (C = A @ B^T).
// Tiles: 128x128x16, 256 threads (8 warps, each 64x32), double-buffered cp.async.
template<bool BT, int ACT, bool RES>
__global__ __launch_bounds__(256) void tgemm_kernel(
    const float* __restrict__ A, const float* __restrict__ B,
    const float* __restrict__ bias, const float* __restrict__ resid,
    float* __restrict__ C, int M, int Nn, int K, float scale)
{
    constexpr int BM = 128, BN = 128, BK = 16;
    constexpr int AP  = 20;   // A smem row pad (floats)
    constexpr int BPF = 132;  // B smem row pad, BT=false ([BK][BPF])
    constexpr int BPT = 20;   // B smem row pad, BT=true  ([BN][BPT])
    constexpr int BS_ELEMS = BT ? (BN * BPT) : (BK * BPF);

    __shared__ float As[2][BM * AP];
    __shared__ float Bs[2][BS_ELEMS];

    int tid  = threadIdx.x;
    int wid  = tid >> 5;
    int lane = tid & 31;
    int grp  = lane >> 2;     // 0..7
    int tig  = lane & 3;      // 0..3
    int wm = (wid & 1) * 64;  // warp m-offset in tile
    int wn = (wid >> 1) * 32; // warp n-offset in tile
    int bm = blockIdx.y * BM;
    int bn = blockIdx.x * BN;

    float acc[4][4][4];
    #pragma unroll
    for (int i = 0; i < 4; i++)
        #pragma unroll
        for (int j = 0; j < 4; j++)
            #pragma unroll
            for (int c = 0; c < 4; c++) acc[i][j][c] = 0.0f;

    auto loadTile = [&](int s, int k0) {
        #pragma unroll
        for (int it = 0; it < 2; it++) {
            int idx = tid + it * 256;       // 0..511
            int m = idx >> 2;               // 0..127
            int kc = (idx & 3) << 2;        // 0,4,8,12
            cp_async16(&As[s][m * AP + kc], A + (size_t)(bm + m) * K + k0 + kc);
        }
        if (BT) {
            #pragma unroll
            for (int it = 0; it < 2; it++) {
                int idx = tid + it * 256;
                int n = idx >> 2;
                int kc = (idx & 3) << 2;
                cp_async16(&Bs[s][n * BPT + kc], B + (size_t)(bn + n) * K + k0 + kc);
            }
        } else {
            #pragma unroll
            for (int it = 0; it < 2; it++) {
                int idx = tid + it * 256;
                int kr = idx >> 5;              // 0..15
                int nc = (idx & 31) << 2;       // 0..124
                cp_async16(&Bs[s][kr * BPF + nc], B + (size_t)(k0 + kr) * Nn + bn + nc);
            }
        }
        cp_commit();
    };

    loadTile(0, 0);
    int nt = K / BK;

    for (int t = 0; t < nt; t++) {
        int s = t & 1;
        if (t + 1 < nt) {
            loadTile(s ^ 1, (t + 1) * BK);
            cp_wait<1>();
        } else {
            cp_wait<0>();
        }
        __syncthreads();

        #pragma unroll
        for (int ks = 0; ks < 2; ks++) {
            uint32_t af[4][4];
            uint32_t bf[4][2];
            #pragma unroll
            for (int mi = 0; mi < 4; mi++) {
                const float* ap = &As[s][(wm + mi * 16 + grp) * AP + ks * 8 + tig];
                af[mi][0] = f2tf32(ap[0]);           // (row g,   col tig)
                af[mi][1] = f2tf32(ap[8 * AP]);      // (row g+8, col tig)
                af[mi][2] = f2tf32(ap[4]);           // (row g,   col tig+4)
                af[mi][3] = f2tf32(ap[8 * AP + 4]);  // (row g+8, col tig+4)
            }
            #pragma unroll
            for (int ni = 0; ni < 4; ni++) {
                if (BT) {
                    const float* bp = &Bs[s][(wn + ni * 8 + grp) * BPT + ks * 8 + tig];
                    bf[ni][0] = f2tf32(bp[0]);       // (k tig,   n g)
                    bf[ni][1] = f2tf32(bp[4]);       // (k tig+4, n g)
                } else {
                    const float* bp = &Bs[s][(ks * 8 + tig) * BPF + wn + ni * 8 + grp];
                    bf[ni][0] = f2tf32(bp[0]);
                    bf[ni][1] = f2tf32(bp[4 * BPF]);
                }
            }
            #pragma unroll
            for (int mi = 0; mi < 4; mi++)
                #pragma unroll
                for (int ni = 0; ni < 4; ni++)
                    mma_tf32(acc[mi][ni], af[mi], bf[ni]);
        }
        __syncthreads();
    }

    // epilogue: c0=(g,2t) c1=(g,2t+1) c2=(g+8,2t) c3=(g+8,2t+1)
    #pragma unroll
    for (int mi = 0; mi < 4; mi++) {
        #pragma unroll
        for (int ni = 0; ni < 4; ni++) {
            int col = bn + wn + ni * 8 + 2 * tig;
            float b0v = bias ? bias[col]     : 0.0f;
            float b1v = bias ? bias[col + 1] : 0.0f;
            #pragma unroll
            for (int rr = 0; rr < 2; rr++) {
                int row = bm + wm + mi * 16 + grp + rr * 8;
                float v0 = acc[mi][ni][rr * 2 + 0] * scale + b0v;
                float v1 = acc[mi][ni][rr * 2 + 1] * scale + b1v;
                if (ACT == 1) {
                    v0 = (v0 > 0.0f) ? v0 : 0.1f * v0;
                    v1 = (v1 > 0.0f) ? v1 : 0.1f * v1;
                }
                size_t off = (size_t)row * Nn + col;
                if (RES) { v0 += resid[off]; v1 += resid[off + 1]; }
                float2 o = make_float2(v0, v1);
                *(float2*)(C + off) = o;
            }
        }
    }
}

// ---------------- host side ----------------
extern "C" void kernel_launch(void* const* d_in, const int* in_sizes, int n_in,
                              void* d_out, int out_size) {
    const float* x      = (const float*)d_in[0];
    const float* norm_g = (const float*)d_in[1];
    const float* norm_b = (const float*)d_in[2];
    const float* Wq = (const float*)d_in[3];
    const float* bq = (const float*)d_in[4];
    const float* Wk = (const float*)d_in[5];
    const float* bk = (const float*)d_in[6];
    const float* Wv = (const float*)d_in[7];
    const float* bv = (const float*)d_in[8];
    const float* W1 = (const float*)d_in[9];
    const float* b1 = (const float*)d_in[10];
    const float* W2 = (const float*)d_in[11];
    const float* b2 = (const float*)d_in[12];
    float* out = (float*)d_out;

    float *xn, *q, *k, *v, *s, *h, *m;
    cudaGetSymbolAddress((void**)&xn, g_xn);
    cudaGetSymbolAddress((void**)&q,  g_q);
    cudaGetSymbolAddress((void**)&k,  g_k);
    cudaGetSymbolAddress((void**)&v,  g_v);
    cudaGetSymbolAddress((void**)&s,  g_s);
    cudaGetSymbolAddress((void**)&h,  g_h);
    cudaGetSymbolAddress((void**)&m,  g_m);

    // 1. LayerNorm (writes g_xn)
    ln_kernel<<<SQ, 256>>>(x, norm_g, norm_b);

    // 2. q/k/v projections: [SQ,ND] @ [ND,ND] + b
    dim3 gNN(ND / 128, SQ / 128);
    tgemm_kernel<false, 0, false><<<gNN, 256>>>(xn, Wq, bq, nullptr, q, SQ, ND, ND, 1.0f);
    tgemm_kernel<false, 0, false><<<gNN, 256>>>(xn, Wk, bk, nullptr, k, SQ, ND, ND, 1.0f);
    tgemm_kernel<false, 0, false><<<gNN, 256>>>(xn, Wv, bv, nullptr, v, SQ, ND, ND, 1.0f);

    // 3. scores = (k @ q^T) / sqrt(N) -> [SQ, SQ]
    dim3 gSS(SQ / 128, SQ / 128);
    tgemm_kernel<true, 0, false><<<gSS, 256>>>(k, q, nullptr, nullptr, s, SQ, SQ, ND, 0.03125f);

    // 4. softmax rows (in-place on g_s)
    softmax_kernel<<<SQ, 256>>>();

    // 5. h = P @ v  [SQ,SQ] @ [SQ,ND]
    tgemm_kernel<false, 0, false><<<gNN, 256>>>(s, v, nullptr, nullptr, h, SQ, ND, SQ, 1.0f);

    // 6. mid = leaky_relu(h @ W1 + b1)  [SQ,ND] @ [ND,FD]
    dim3 gNF(FD / 128, SQ / 128);
    tgemm_kernel<false, 1, false><<<gNF, 256>>>(h, W1, b1, nullptr, m, SQ, FD, ND, 1.0f);

    // 7. out = mid @ W2 + b2 + xn  [SQ,FD] @ [FD,ND]
    tgemm_kernel<false, 0, true><<<gNN, 256>>>(m, W2, b2, xn, out, SQ, ND, FD, 1.0f);
}

// round 4
// speedup vs baseline: 3.3864x; 1.1439x over previous
#include <cuda_runtime.h>
#include <cstdint>

#define SQ 4096      // sequence length S
#define ND 1024      // model dim N
#define FD 4096      // ffn dim 4N

// ---------------- scratch (allocation-free: static device globals) ----------
__device__ float g_xn[(size_t)SQ * ND];   // 16 MB
__device__ float g_q [(size_t)SQ * ND];
__device__ float g_k [(size_t)SQ * ND];
__device__ float g_v [(size_t)SQ * ND];
__device__ float g_s [(size_t)SQ * SQ];   // 64 MB scores / probs
__device__ float g_h [(size_t)SQ * ND];
__device__ float g_m [(size_t)SQ * FD];   // 64 MB ffn mid

// ---------------- small helpers ----------------
__device__ __forceinline__ float warpSum(float v) {
    #pragma unroll
    for (int o = 16; o; o >>= 1) v += __shfl_xor_sync(0xffffffffu, v, o);
    return v;
}
__device__ __forceinline__ float warpMax(float v) {
    #pragma unroll
    for (int o = 16; o; o >>= 1) v = fmaxf(v, __shfl_xor_sync(0xffffffffu, v, o));
    return v;
}

__device__ __forceinline__ void cp_async16(void* smem_dst, const void* gmem_src) {
    uint32_t s = (uint32_t)__cvta_generic_to_shared(smem_dst);
    asm volatile("cp.async.cg.shared.global [%0], [%1], 16;" :: "r"(s), "l"(gmem_src));
}
__device__ __forceinline__ void cp_commit() {
    asm volatile("cp.async.commit_group;" ::: "memory");
}
template<int NN>
__device__ __forceinline__ void cp_wait() {
    asm volatile("cp.async.wait_group %0;" :: "n"(NN) : "memory");
}

__device__ __forceinline__ void mma_tf32(float* c, const uint32_t* a, const uint32_t* b) {
    asm volatile(
        "mma.sync.aligned.m16n8k8.row.col.f32.tf32.tf32.f32 "
        "{%0,%1,%2,%3}, {%4,%5,%6,%7}, {%8,%9}, {%0,%1,%2,%3};"
        : "+f"(c[0]), "+f"(c[1]), "+f"(c[2]), "+f"(c[3])
        : "r"(a[0]), "r"(a[1]), "r"(a[2]), "r"(a[3]), "r"(b[0]), "r"(b[1]));
}

// ---------------- LayerNorm ----------------
__global__ __launch_bounds__(256) void ln_kernel(const float* __restrict__ x,
                          const float* __restrict__ g,
                          const float* __restrict__ b) {
    int row = blockIdx.x;
    int t = threadIdx.x;
    const float4* xr = (const float4*)(x + (size_t)row * ND);
    float4 xv = xr[t];
    float s1 = xv.x + xv.y + xv.z + xv.w;
    float s2 = xv.x*xv.x + xv.y*xv.y + xv.z*xv.z + xv.w*xv.w;

    __shared__ float shA[8], shB[8];
    s1 = warpSum(s1); s2 = warpSum(s2);
    if ((t & 31) == 0) { shA[t >> 5] = s1; shB[t >> 5] = s2; }
    __syncthreads();
    if (t < 32) {
        float a = (t < 8) ? shA[t] : 0.0f;
        float c = (t < 8) ? shB[t] : 0.0f;
        a = warpSum(a); c = warpSum(c);
        if (t == 0) { shA[0] = a; shB[0] = c; }
    }
    __syncthreads();
    float mu  = shA[0] * (1.0f / ND);
    float var = shB[0] * (1.0f / ND) - mu * mu;
    float rstd = rsqrtf(var + 1e-5f);

    float4 gv = ((const float4*)g)[t];
    float4 bv = ((const float4*)b)[t];
    float4 o;
    o.x = (xv.x - mu) * rstd * gv.x + bv.x;
    o.y = (xv.y - mu) * rstd * gv.y + bv.y;
    o.z = (xv.z - mu) * rstd * gv.z + bv.z;
    o.w = (xv.w - mu) * rstd * gv.w + bv.w;
    ((float4*)(g_xn + (size_t)row * ND))[t] = o;
}

// ---------------- Softmax over rows of length SQ ----------------
__global__ __launch_bounds__(256) void softmax_kernel() {
    int row = blockIdx.x;
    int t = threadIdx.x;
    float4* r = (float4*)(g_s + (size_t)row * SQ);
    float4 v[4];
    float mx = -1e30f;
    #pragma unroll
    for (int i = 0; i < 4; i++) {
        v[i] = r[t + i * 256];
        mx = fmaxf(mx, fmaxf(fmaxf(v[i].x, v[i].y), fmaxf(v[i].z, v[i].w)));
    }
    __shared__ float shA[8], shB[8];
    mx = warpMax(mx);
    if ((t & 31) == 0) shA[t >> 5] = mx;
    __syncthreads();
    if (t < 32) {
        float a = (t < 8) ? shA[t] : -1e30f;
        a = warpMax(a);
        if (t == 0) shA[0] = a;
    }
    __syncthreads();
    mx = shA[0];

    float sum = 0.0f;
    #pragma unroll
    for (int i = 0; i < 4; i++) {
        v[i].x = __expf(v[i].x - mx);
        v[i].y = __expf(v[i].y - mx);
        v[i].z = __expf(v[i].z - mx);
        v[i].w = __expf(v[i].w - mx);
        sum += v[i].x + v[i].y + v[i].z + v[i].w;
    }
    sum = warpSum(sum);
    if ((t & 31) == 0) shB[t >> 5] = sum;
    __syncthreads();
    if (t < 32) {
        float a = (t < 8) ? shB[t] : 0.0f;
        a = warpSum(a);
        if (t == 0) shB[0] = a;
    }
    __syncthreads();
    float inv = 1.0f / shB[0];
    #pragma unroll
    for (int i = 0; i < 4; i++) {
        v[i].x *= inv; v[i].y *= inv; v[i].z *= inv; v[i].w *= inv;
        r[t + i * 256] = v[i];
    }
}

// ---------------- TF32 tensor-core GEMM ----------------
// C[M,Nn] = act(scale * (A @ B) + bias) (+ resid)
// A: [M,K] row-major.
// BT=false: B [K,Nn] row-major.  BT=true: B [Nn,K] row-major (C = A @ B^T).
// Tiles: 128x128x16, 128 threads (4 warps, each 64x64), double-buffered cp.async.
// No explicit tf32 conversion: mma hardware truncates the fp32 mantissa.
template<bool BT, int ACT, bool RES>
__global__ __launch_bounds__(128, 2) void tgemm_kernel(
    const float* __restrict__ A, const float* __restrict__ B,
    const float* __restrict__ bias, const float* __restrict__ resid,
    float* __restrict__ C, int M, int Nn, int K, float scale)
{
    constexpr int BM = 128, BN = 128, BK = 16;
    constexpr int AP  = 20;   // A smem row pad (floats) -> conflict-free frag LDS
    constexpr int BPF = 136;  // B smem row pad, BT=false ([BK][BPF]) -> conflict-free
    constexpr int BPT = 20;   // B smem row pad, BT=true  ([BN][BPT])
    constexpr int BS_ELEMS = BT ? (BN * BPT) : (BK * BPF);

    __shared__ float As[2][BM * AP];
    __shared__ float Bs[2][BS_ELEMS];

    int tid  = threadIdx.x;
    int wid  = tid >> 5;
    int lane = tid & 31;
    int grp  = lane >> 2;     // 0..7
    int tig  = lane & 3;      // 0..3
    int wm = (wid & 1) * 64;  // warp m-offset in tile
    int wn = (wid >> 1) * 64; // warp n-offset in tile
    int bm = blockIdx.y * BM;
    int bn = blockIdx.x * BN;

    float acc[4][8][4];
    #pragma unroll
    for (int i = 0; i < 4; i++)
        #pragma unroll
        for (int j = 0; j < 8; j++)
            #pragma unroll
            for (int c = 0; c < 4; c++) acc[i][j][c] = 0.0f;

    auto loadTile = [&](int s, int k0) {
        #pragma unroll
        for (int it = 0; it < 4; it++) {
            int idx = tid + it * 128;       // 0..511
            int m = idx >> 2;               // 0..127
            int kc = (idx & 3) << 2;        // 0,4,8,12
            cp_async16(&As[s][m * AP + kc], A + (size_t)(bm + m) * K + k0 + kc);
        }
        if (BT) {
            #pragma unroll
            for (int it = 0; it < 4; it++) {
                int idx = tid + it * 128;
                int n = idx >> 2;
                int kc = (idx & 3) << 2;
                cp_async16(&Bs[s][n * BPT + kc], B + (size_t)(bn + n) * K + k0 + kc);
            }
        } else {
            #pragma unroll
            for (int it = 0; it < 4; it++) {
                int idx = tid + it * 128;
                int kr = idx >> 5;              // 0..15
                int nc = (idx & 31) << 2;       // 0..124
                cp_async16(&Bs[s][kr * BPF + nc], B + (size_t)(k0 + kr) * Nn + bn + nc);
            }
        }
        cp_commit();
    };

    loadTile(0, 0);
    int nt = K / BK;

    for (int t = 0; t < nt; t++) {
        int s = t & 1;
        if (t + 1 < nt) {
            loadTile(s ^ 1, (t + 1) * BK);
            cp_wait<1>();
        } else {
            cp_wait<0>();
        }
        __syncthreads();

        #pragma unroll
        for (int ks = 0; ks < 2; ks++) {
            uint32_t af[4][4];
            uint32_t bf[8][2];
            #pragma unroll
            for (int mi = 0; mi < 4; mi++) {
                const float* ap = &As[s][(wm + mi * 16 + grp) * AP + ks * 8 + tig];
                af[mi][0] = __float_as_uint(ap[0]);           // (row g,   col tig)
                af[mi][1] = __float_as_uint(ap[8 * AP]);      // (row g+8, col tig)
                af[mi][2] = __float_as_uint(ap[4]);           // (row g,   col tig+4)
                af[mi][3] = __float_as_uint(ap[8 * AP + 4]);  // (row g+8, col tig+4)
            }
            #pragma unroll
            for (int ni = 0; ni < 8; ni++) {
                if (BT) {
                    const float* bp = &Bs[s][(wn + ni * 8 + grp) * BPT + ks * 8 + tig];
                    bf[ni][0] = __float_as_uint(bp[0]);       // (k tig,   n g)
                    bf[ni][1] = __float_as_uint(bp[4]);       // (k tig+4, n g)
                } else {
                    const float* bp = &Bs[s][(ks * 8 + tig) * BPF + wn + ni * 8 + grp];
                    bf[ni][0] = __float_as_uint(bp[0]);
                    bf[ni][1] = __float_as_uint(bp[4 * BPF]);
                }
            }
            #pragma unroll
            for (int mi = 0; mi < 4; mi++)
                #pragma unroll
                for (int ni = 0; ni < 8; ni++)
                    mma_tf32(acc[mi][ni], af[mi], bf[ni]);
        }
        __syncthreads();
    }

    // epilogue: c0=(g,2t) c1=(g,2t+1) c2=(g+8,2t) c3=(g+8,2t+1)
    #pragma unroll
    for (int mi = 0; mi < 4; mi++) {
        #pragma unroll
        for (int ni = 0; ni < 8; ni++) {
            int col = bn + wn + ni * 8 + 2 * tig;
            float b0v = bias ? bias[col]     : 0.0f;
            float b1v = bias ? bias[col + 1] : 0.0f;
            #pragma unroll
            for (int rr = 0; rr < 2; rr++) {
                int row = bm + wm + mi * 16 + grp + rr * 8;
                float v0 = acc[mi][ni][rr * 2 + 0] * scale + b0v;
                float v1 = acc[mi][ni][rr * 2 + 1] * scale + b1v;
                if (ACT == 1) {
                    v0 = (v0 > 0.0f) ? v0 : 0.1f * v0;
                    v1 = (v1 > 0.0f) ? v1 : 0.1f * v1;
                }
                size_t off = (size_t)row * Nn + col;
                if (RES) { v0 += resid[off]; v1 += resid[off + 1]; }
                float2 o = make_float2(v0, v1);
                *(float2*)(C + off) = o;
            }
        }
    }
}

// ---------------- host side ----------------
extern "C" void kernel_launch(void* const* d_in, const int* in_sizes, int n_in,
                              void* d_out, int out_size) {
    const float* x      = (const float*)d_in[0];
    const float* norm_g = (const float*)d_in[1];
    const float* norm_b = (const float*)d_in[2];
    const float* Wq = (const float*)d_in[3];
    const float* bq = (const float*)d_in[4];
    const float* Wk = (const float*)d_in[5];
    const float* bk = (const float*)d_in[6];
    const float* Wv = (const float*)d_in[7];
    const float* bv = (const float*)d_in[8];
    const float* W1 = (const float*)d_in[9];
    const float* b1 = (const float*)d_in[10];
    const float* W2 = (const float*)d_in[11];
    const float* b2 = (const float*)d_in[12];
    float* out = (float*)d_out;

    float *xn, *q, *k, *v, *s, *h, *m;
    cudaGetSymbolAddress((void**)&xn, g_xn);
    cudaGetSymbolAddress((void**)&q,  g_q);
    cudaGetSymbolAddress((void**)&k,  g_k);
    cudaGetSymbolAddress((void**)&v,  g_v);
    cudaGetSymbolAddress((void**)&s,  g_s);
    cudaGetSymbolAddress((void**)&h,  g_h);
    cudaGetSymbolAddress((void**)&m,  g_m);

    // 1. LayerNorm (writes g_xn)
    ln_kernel<<<SQ, 256>>>(x, norm_g, norm_b);

    // 2. q/k/v projections: [SQ,ND] @ [ND,ND] + b
    dim3 gNN(ND / 128, SQ / 128);
    tgemm_kernel<false, 0, false><<<gNN, 128>>>(xn, Wq, bq, nullptr, q, SQ, ND, ND, 1.0f);
    tgemm_kernel<false, 0, false><<<gNN, 128>>>(xn, Wk, bk, nullptr, k, SQ, ND, ND, 1.0f);
    tgemm_kernel<false, 0, false><<<gNN, 128>>>(xn, Wv, bv, nullptr, v, SQ, ND, ND, 1.0f);

    // 3. scores = (k @ q^T) / sqrt(N) -> [SQ, SQ]
    dim3 gSS(SQ / 128, SQ / 128);
    tgemm_kernel<true, 0, false><<<gSS, 128>>>(k, q, nullptr, nullptr, s, SQ, SQ, ND, 0.03125f);

    // 4. softmax rows (in-place on g_s)
    softmax_kernel<<<SQ, 256>>>();

    // 5. h = P @ v  [SQ,SQ] @ [SQ,ND]
    tgemm_kernel<false, 0, false><<<gNN, 128>>>(s, v, nullptr, nullptr, h, SQ, ND, SQ, 1.0f);

    // 6. mid = leaky_relu(h @ W1 + b1)  [SQ,ND] @ [ND,FD]
    dim3 gNF(FD / 128, SQ / 128);
    tgemm_kernel<false, 1, false><<<gNF, 128>>>(h, W1, b1, nullptr, m, SQ, FD, ND, 1.0f);

    // 7. out = mid @ W2 + b2 + xn  [SQ,FD] @ [FD,ND]
    tgemm_kernel<false, 0, true><<<gNN, 128>>>(m, W2, b2, xn, out, SQ, ND, FD, 1.0f);
}

// round 5
// speedup vs baseline: 3.6508x; 1.0781x over previous
#include <cuda_runtime.h>
#include <cstdint>

#define SQ 4096      // sequence length S
#define ND 1024      // model dim N
#define FD 4096      // ffn dim 4N

// ---------------- scratch (allocation-free: static device globals) ----------
__device__ float g_xn[(size_t)SQ * ND];   // 16 MB
__device__ float g_q [(size_t)SQ * ND];
__device__ float g_k [(size_t)SQ * ND];
__device__ float g_v [(size_t)SQ * ND];
__device__ float g_s [(size_t)SQ * SQ];   // 64 MB scores / probs
__device__ float g_h [(size_t)SQ * ND];
__device__ float g_m [(size_t)SQ * FD];   // 64 MB ffn mid

// ---------------- small helpers ----------------
__device__ __forceinline__ float warpSum(float v) {
    #pragma unroll
    for (int o = 16; o; o >>= 1) v += __shfl_xor_sync(0xffffffffu, v, o);
    return v;
}
__device__ __forceinline__ float warpMax(float v) {
    #pragma unroll
    for (int o = 16; o; o >>= 1) v = fmaxf(v, __shfl_xor_sync(0xffffffffu, v, o));
    return v;
}

__device__ __forceinline__ void cp_async16(void* smem_dst, const void* gmem_src) {
    uint32_t s = (uint32_t)__cvta_generic_to_shared(smem_dst);
    asm volatile("cp.async.cg.shared.global [%0], [%1], 16;" :: "r"(s), "l"(gmem_src));
}
__device__ __forceinline__ void cp_commit() {
    asm volatile("cp.async.commit_group;" ::: "memory");
}
template<int NN>
__device__ __forceinline__ void cp_wait() {
    asm volatile("cp.async.wait_group %0;" :: "n"(NN) : "memory");
}

__device__ __forceinline__ void mma_tf32(float* c, const uint32_t* a, const uint32_t* b) {
    asm volatile(
        "mma.sync.aligned.m16n8k8.row.col.f32.tf32.tf32.f32 "
        "{%0,%1,%2,%3}, {%4,%5,%6,%7}, {%8,%9}, {%0,%1,%2,%3};"
        : "+f"(c[0]), "+f"(c[1]), "+f"(c[2]), "+f"(c[3])
        : "r"(a[0]), "r"(a[1]), "r"(a[2]), "r"(a[3]), "r"(b[0]), "r"(b[1]));
}

// ---------------- LayerNorm ----------------
__global__ __launch_bounds__(256) void ln_kernel(const float* __restrict__ x,
                          const float* __restrict__ g,
                          const float* __restrict__ b) {
    int row = blockIdx.x;
    int t = threadIdx.x;
    const float4* xr = (const float4*)(x + (size_t)row * ND);
    float4 xv = xr[t];
    float s1 = xv.x + xv.y + xv.z + xv.w;
    float s2 = xv.x*xv.x + xv.y*xv.y + xv.z*xv.z + xv.w*xv.w;

    __shared__ float shA[8], shB[8];
    s1 = warpSum(s1); s2 = warpSum(s2);
    if ((t & 31) == 0) { shA[t >> 5] = s1; shB[t >> 5] = s2; }
    __syncthreads();
    if (t < 32) {
        float a = (t < 8) ? shA[t] : 0.0f;
        float c = (t < 8) ? shB[t] : 0.0f;
        a = warpSum(a); c = warpSum(c);
        if (t == 0) { shA[0] = a; shB[0] = c; }
    }
    __syncthreads();
    float mu  = shA[0] * (1.0f / ND);
    float var = shB[0] * (1.0f / ND) - mu * mu;
    float rstd = rsqrtf(var + 1e-5f);

    float4 gv = ((const float4*)g)[t];
    float4 bv = ((const float4*)b)[t];
    float4 o;
    o.x = (xv.x - mu) * rstd * gv.x + bv.x;
    o.y = (xv.y - mu) * rstd * gv.y + bv.y;
    o.z = (xv.z - mu) * rstd * gv.z + bv.z;
    o.w = (xv.w - mu) * rstd * gv.w + bv.w;
    ((float4*)(g_xn + (size_t)row * ND))[t] = o;
}

// ---------------- Softmax over rows of length SQ ----------------
__global__ __launch_bounds__(256) void softmax_kernel() {
    int row = blockIdx.x;
    int t = threadIdx.x;
    float4* r = (float4*)(g_s + (size_t)row * SQ);
    float4 v[4];
    float mx = -1e30f;
    #pragma unroll
    for (int i = 0; i < 4; i++) {
        v[i] = r[t + i * 256];
        mx = fmaxf(mx, fmaxf(fmaxf(v[i].x, v[i].y), fmaxf(v[i].z, v[i].w)));
    }
    __shared__ float shA[8], shB[8];
    mx = warpMax(mx);
    if ((t & 31) == 0) shA[t >> 5] = mx;
    __syncthreads();
    if (t < 32) {
        float a = (t < 8) ? shA[t] : -1e30f;
        a = warpMax(a);
        if (t == 0) shA[0] = a;
    }
    __syncthreads();
    mx = shA[0];

    float sum = 0.0f;
    #pragma unroll
    for (int i = 0; i < 4; i++) {
        v[i].x = __expf(v[i].x - mx);
        v[i].y = __expf(v[i].y - mx);
        v[i].z = __expf(v[i].z - mx);
        v[i].w = __expf(v[i].w - mx);
        sum += v[i].x + v[i].y + v[i].z + v[i].w;
    }
    sum = warpSum(sum);
    if ((t & 31) == 0) shB[t >> 5] = sum;
    __syncthreads();
    if (t < 32) {
        float a = (t < 8) ? shB[t] : 0.0f;
        a = warpSum(a);
        if (t == 0) shB[0] = a;
    }
    __syncthreads();
    float inv = 1.0f / shB[0];
    #pragma unroll
    for (int i = 0; i < 4; i++) {
        v[i].x *= inv; v[i].y *= inv; v[i].z *= inv; v[i].w *= inv;
        r[t + i * 256] = v[i];
    }
}

// ---------------- TF32 tensor-core GEMM ----------------
// C[M,Nn] = act(scale * (A @ B) + bias) (+ resid)
// A: [M,K] row-major.
// BT=false: B [K,Nn] row-major.  BT=true: B [Nn,K] row-major (C = A @ B^T).
// Tiles: 128x128x16, 128 threads (4 warps, each 64x64).
// 3-stage cp.async pipeline, ONE __syncthreads per k-tile (loads issued at the
// END of the compute phase so the single barrier covers both hazards).
template<bool BT, int ACT, bool RES>
__global__ __launch_bounds__(128, 2) void tgemm_kernel(
    const float* __restrict__ A, const float* __restrict__ B,
    const float* __restrict__ bias, const float* __restrict__ resid,
    float* __restrict__ C, int M, int Nn, int K, float scale)
{
    constexpr int BM = 128, BN = 128, BK = 16;
    constexpr int AP  = 20;   // A smem row pad (floats) -> conflict-free frag LDS
    constexpr int BPF = 136;  // B smem row pad, BT=false ([BK][BPF]) -> conflict-free
    constexpr int BPT = 20;   // B smem row pad, BT=true  ([BN][BPT])
    constexpr int AST = BM * AP;                       // A floats per stage
    constexpr int BST = BT ? (BN * BPT) : (BK * BPF);  // B floats per stage

    extern __shared__ float smem[];
    float* Asm = smem;             // [3][AST]
    float* Bsm = smem + 3 * AST;   // [3][BST]

    int tid  = threadIdx.x;
    int wid  = tid >> 5;
    int lane = tid & 31;
    int grp  = lane >> 2;     // 0..7
    int tig  = lane & 3;      // 0..3
    int wm = (wid & 1) * 64;  // warp m-offset in tile
    int wn = (wid >> 1) * 64; // warp n-offset in tile
    int bm = blockIdx.y * BM;
    int bn = blockIdx.x * BN;

    float acc[4][8][4];
    #pragma unroll
    for (int i = 0; i < 4; i++)
        #pragma unroll
        for (int j = 0; j < 8; j++)
            #pragma unroll
            for (int c = 0; c < 4; c++) acc[i][j][c] = 0.0f;

    auto loadTile = [&](int s, int k0) {
        float* As = Asm + s * AST;
        float* Bs = Bsm + s * BST;
        #pragma unroll
        for (int it = 0; it < 4; it++) {
            int idx = tid + it * 128;       // 0..511
            int m = idx >> 2;               // 0..127
            int kc = (idx & 3) << 2;        // 0,4,8,12
            cp_async16(&As[m * AP + kc], A + (size_t)(bm + m) * K + k0 + kc);
        }
        if (BT) {
            #pragma unroll
            for (int it = 0; it < 4; it++) {
                int idx = tid + it * 128;
                int n = idx >> 2;
                int kc = (idx & 3) << 2;
                cp_async16(&Bs[n * BPT + kc], B + (size_t)(bn + n) * K + k0 + kc);
            }
        } else {
            #pragma unroll
            for (int it = 0; it < 4; it++) {
                int idx = tid + it * 128;
                int kr = idx >> 5;              // 0..15
                int nc = (idx & 31) << 2;       // 0..124
                cp_async16(&Bs[kr * BPF + nc], B + (size_t)(k0 + kr) * Nn + bn + nc);
            }
        }
        cp_commit();
    };

    int nt = K / BK;     // >= 2 always here (K = 1024 or 4096)
    loadTile(0, 0);
    loadTile(1, BK);

    int s = 0;           // compute stage
    int sl = 2;          // next load stage
    for (int t = 0; t < nt; t++) {
        if (t + 1 < nt) cp_wait<1>(); else cp_wait<0>();
        __syncthreads();

        const float* As = Asm + s * AST;
        const float* Bs = Bsm + s * BST;

        #pragma unroll
        for (int ks = 0; ks < 2; ks++) {
            uint32_t af[4][4];
            uint32_t bf[8][2];
            #pragma unroll
            for (int mi = 0; mi < 4; mi++) {
                const float* ap = &As[(wm + mi * 16 + grp) * AP + ks * 8 + tig];
                af[mi][0] = __float_as_uint(ap[0]);           // (row g,   col tig)
                af[mi][1] = __float_as_uint(ap[8 * AP]);      // (row g+8, col tig)
                af[mi][2] = __float_as_uint(ap[4]);           // (row g,   col tig+4)
                af[mi][3] = __float_as_uint(ap[8 * AP + 4]);  // (row g+8, col tig+4)
            }
            #pragma unroll
            for (int ni = 0; ni < 8; ni++) {
                if (BT) {
                    const float* bp = &Bs[(wn + ni * 8 + grp) * BPT + ks * 8 + tig];
                    bf[ni][0] = __float_as_uint(bp[0]);       // (k tig,   n g)
                    bf[ni][1] = __float_as_uint(bp[4]);       // (k tig+4, n g)
                } else {
                    const float* bp = &Bs[(ks * 8 + tig) * BPF + wn + ni * 8 + grp];
                    bf[ni][0] = __float_as_uint(bp[0]);
                    bf[ni][1] = __float_as_uint(bp[4 * BPF]);
                }
            }
            #pragma unroll
            for (int mi = 0; mi < 4; mi++)
                #pragma unroll
                for (int ni = 0; ni < 8; ni++)
                    mma_tf32(acc[mi][ni], af[mi], bf[ni]);
        }

        // issue the tile-after-next load; single barrier above covers the
        // WAR hazard (stage sl was last read in iteration t-1).
        if (t + 2 < nt) loadTile(sl, (t + 2) * BK);
        s  = (s  == 2) ? 0 : s + 1;
        sl = (sl == 2) ? 0 : sl + 1;
    }

    // epilogue: c0=(g,2t) c1=(g,2t+1) c2=(g+8,2t) c3=(g+8,2t+1)
    #pragma unroll
    for (int mi = 0; mi < 4; mi++) {
        #pragma unroll
        for (int ni = 0; ni < 8; ni++) {
            int col = bn + wn + ni * 8 + 2 * tig;
            float b0v = bias ? bias[col]     : 0.0f;
            float b1v = bias ? bias[col + 1] : 0.0f;
            #pragma unroll
            for (int rr = 0; rr < 2; rr++) {
                int row = bm + wm + mi * 16 + grp + rr * 8;
                float v0 = acc[mi][ni][rr * 2 + 0] * scale + b0v;
                float v1 = acc[mi][ni][rr * 2 + 1] * scale + b1v;
                if (ACT == 1) {
                    v0 = (v0 > 0.0f) ? v0 : 0.1f * v0;
                    v1 = (v1 > 0.0f) ? v1 : 0.1f * v1;
                }
                size_t off = (size_t)row * Nn + col;
                if (RES) { v0 += resid[off]; v1 += resid[off + 1]; }
                float2 o = make_float2(v0, v1);
                *(float2*)(C + off) = o;
            }
        }
    }
}

// smem bytes per template config
static constexpr int AST_B  = 128 * 20 * 4;          // 10240 per stage
static constexpr int BST_F  = 16 * 136 * 4;          // 8704 per stage
static constexpr int BST_T  = 128 * 20 * 4;          // 10240 per stage
static constexpr int SMEM_F = 3 * (AST_B + BST_F);   // 56832
static constexpr int SMEM_T = 3 * (AST_B + BST_T);   // 61440

// ---------------- host side ----------------
extern "C" void kernel_launch(void* const* d_in, const int* in_sizes, int n_in,
                              void* d_out, int out_size) {
    const float* x      = (const float*)d_in[0];
    const float* norm_g = (const float*)d_in[1];
    const float* norm_b = (const float*)d_in[2];
    const float* Wq = (const float*)d_in[3];
    const float* bq = (const float*)d_in[4];
    const float* Wk = (const float*)d_in[5];
    const float* bk = (const float*)d_in[6];
    const float* Wv = (const float*)d_in[7];
    const float* bv = (const float*)d_in[8];
    const float* W1 = (const float*)d_in[9];
    const float* b1 = (const float*)d_in[10];
    const float* W2 = (const float*)d_in[11];
    const float* b2 = (const float*)d_in[12];
    float* out = (float*)d_out;

    float *xn, *q, *k, *v, *s, *h, *m;
    cudaGetSymbolAddress((void**)&xn, g_xn);
    cudaGetSymbolAddress((void**)&q,  g_q);
    cudaGetSymbolAddress((void**)&k,  g_k);
    cudaGetSymbolAddress((void**)&v,  g_v);
    cudaGetSymbolAddress((void**)&s,  g_s);
    cudaGetSymbolAddress((void**)&h,  g_h);
    cudaGetSymbolAddress((void**)&m,  g_m);

    // opt in to >48KB dynamic smem (idempotent, capture-safe, no allocation)
    cudaFuncSetAttribute(tgemm_kernel<false, 0, false>,
                         cudaFuncAttributeMaxDynamicSharedMemorySize, SMEM_F);
    cudaFuncSetAttribute(tgemm_kernel<true, 0, false>,
                         cudaFuncAttributeMaxDynamicSharedMemorySize, SMEM_T);
    cudaFuncSetAttribute(tgemm_kernel<false, 1, false>,
                         cudaFuncAttributeMaxDynamicSharedMemorySize, SMEM_F);
    cudaFuncSetAttribute(tgemm_kernel<false, 0, true>,
                         cudaFuncAttributeMaxDynamicSharedMemorySize, SMEM_F);

    // 1. LayerNorm (writes g_xn)
    ln_kernel<<<SQ, 256>>>(x, norm_g, norm_b);

    // 2. q/k/v projections: [SQ,ND] @ [ND,ND] + b
    dim3 gNN(ND / 128, SQ / 128);
    tgemm_kernel<false, 0, false><<<gNN, 128, SMEM_F>>>(xn, Wq, bq, nullptr, q, SQ, ND, ND, 1.0f);
    tgemm_kernel<false, 0, false><<<gNN, 128, SMEM_F>>>(xn, Wk, bk, nullptr, k, SQ, ND, ND, 1.0f);
    tgemm_kernel<false, 0, false><<<gNN, 128, SMEM_F>>>(xn, Wv, bv, nullptr, v, SQ, ND, ND, 1.0f);

    // 3. scores = (k @ q^T) / sqrt(N) -> [SQ, SQ]
    dim3 gSS(SQ / 128, SQ / 128);
    tgemm_kernel<true, 0, false><<<gSS, 128, SMEM_T>>>(k, q, nullptr, nullptr, s, SQ, SQ, ND, 0.03125f);

    // 4. softmax rows (in-place on g_s)
    softmax_kernel<<<SQ, 256>>>();

    // 5. h = P @ v  [SQ,SQ] @ [SQ,ND]
    tgemm_kernel<false, 0, false><<<gNN, 128, SMEM_F>>>(s, v, nullptr, nullptr, h, SQ, ND, SQ, 1.0f);

    // 6. mid = leaky_relu(h @ W1 + b1)  [SQ,ND] @ [ND,FD]
    dim3 gNF(FD / 128, SQ / 128);
    tgemm_kernel<false, 1, false><<<gNF, 128, SMEM_F>>>(h, W1, b1, nullptr, m, SQ, FD, ND, 1.0f);

    // 7. out = mid @ W2 + b2 + xn  [SQ,FD] @ [FD,ND]
    tgemm_kernel<false, 0, true><<<gNN, 128, SMEM_F>>>(m, W2, b2, xn, out, SQ, ND, FD, 1.0f);
}

// round 8
// speedup vs baseline: 6.4681x; 1.7717x over previous
#include <cuda_runtime.h>
#include <cuda_fp16.h>
#include <cstdint>

#define SQ 4096      // sequence length S
#define ND 1024      // model dim N
#define FD 4096      // ffn dim 4N

// ---------------- scratch (allocation-free: static device globals) ----------
__device__ float  g_xn [(size_t)SQ * ND];           // fp32 normed x (residual)
__device__ __half g_xnh[(size_t)SQ * ND];           // fp16 normed x (GEMM A)
__device__ __half g_qh [(size_t)SQ * ND];
__device__ __half g_kh [(size_t)SQ * ND];
__device__ __half g_vT [(size_t)ND * SQ];           // v transposed [n][s]
__device__ float  g_s  [(size_t)SQ * SQ];           // fp32 scores
__device__ __half g_p  [(size_t)SQ * SQ];           // fp16 probs
__device__ __half g_h  [(size_t)SQ * ND];
__device__ __half g_mid[(size_t)SQ * FD];
// pre-transposed fp16 weights WT[n][k]
__device__ __half g_wqT[(size_t)ND * ND];
__device__ __half g_wkT[(size_t)ND * ND];
__device__ __half g_wvT[(size_t)ND * ND];
__device__ __half g_w1T[(size_t)FD * ND];
__device__ __half g_w2T[(size_t)ND * FD];

// ---------------- helpers ----------------
__device__ __forceinline__ float warpSum(float v) {
    #pragma unroll
    for (int o = 16; o; o >>= 1) v += __shfl_xor_sync(0xffffffffu, v, o);
    return v;
}
__device__ __forceinline__ float warpMax(float v) {
    #pragma unroll
    for (int o = 16; o; o >>= 1) v = fmaxf(v, __shfl_xor_sync(0xffffffffu, v, o));
    return v;
}
__device__ __forceinline__ void cp_async16(void* smem_dst, const void* gmem_src) {
    uint32_t s = (uint32_t)__cvta_generic_to_shared(smem_dst);
    asm volatile("cp.async.cg.shared.global [%0], [%1], 16;" :: "r"(s), "l"(gmem_src));
}
__device__ __forceinline__ void cp_commit() {
    asm volatile("cp.async.commit_group;" ::: "memory");
}
template<int NN>
__device__ __forceinline__ void cp_wait() {
    asm volatile("cp.async.wait_group %0;" :: "n"(NN) : "memory");
}
__device__ __forceinline__ void mma_f16(float* c, const uint32_t* a, const uint32_t* b) {
    asm volatile(
        "mma.sync.aligned.m16n8k16.row.col.f32.f16.f16.f32 "
        "{%0,%1,%2,%3}, {%4,%5,%6,%7}, {%8,%9}, {%0,%1,%2,%3};"
        : "+f"(c[0]), "+f"(c[1]), "+f"(c[2]), "+f"(c[3])
        : "r"(a[0]), "r"(a[1]), "r"(a[2]), "r"(a[3]), "r"(b[0]), "r"(b[1]));
}

// ---------------- weight prep: W[K,N] fp32 -> WT[N,K] fp16 ------------------
__global__ __launch_bounds__(256) void wprep_kernel(const float* __restrict__ W,
                                                    __half* __restrict__ T,
                                                    int K, int N) {
    __shared__ float tile[32][33];
    int n0 = blockIdx.x * 32;
    int k0 = blockIdx.y * 32;
    int tx = threadIdx.x & 31;
    int ty = threadIdx.x >> 5;     // 0..7
    #pragma unroll
    for (int i = 0; i < 4; i++) {
        int r = ty + i * 8;
        tile[r][tx] = W[(size_t)(k0 + r) * N + n0 + tx];
    }
    __syncthreads();
    #pragma unroll
    for (int i = 0; i < 4; i++) {
        int r = ty + i * 8;
        T[(size_t)(n0 + r) * K + k0 + tx] = __float2half_rn(tile[tx][r]);
    }
}

// ---------------- LayerNorm: fp32 out + fp16 out ----------------------------
__global__ __launch_bounds__(256) void ln_kernel(const float* __restrict__ x,
                                                 const float* __restrict__ g,
                                                 const float* __restrict__ b) {
    int row = blockIdx.x;
    int t = threadIdx.x;
    const float4* xr = (const float4*)(x + (size_t)row * ND);
    float4 xv = xr[t];
    float s1 = xv.x + xv.y + xv.z + xv.w;
    float s2 = xv.x*xv.x + xv.y*xv.y + xv.z*xv.z + xv.w*xv.w;

    __shared__ float shA[8], shB[8];
    s1 = warpSum(s1); s2 = warpSum(s2);
    if ((t & 31) == 0) { shA[t >> 5] = s1; shB[t >> 5] = s2; }
    __syncthreads();
    if (t < 32) {
        float a = (t < 8) ? shA[t] : 0.0f;
        float c = (t < 8) ? shB[t] : 0.0f;
        a = warpSum(a); c = warpSum(c);
        if (t == 0) { shA[0] = a; shB[0] = c; }
    }
    __syncthreads();
    float mu  = shA[0] * (1.0f / ND);
    float var = shB[0] * (1.0f / ND) - mu * mu;
    float rstd = rsqrtf(var + 1e-5f);

    float4 gv = ((const float4*)g)[t];
    float4 bv = ((const float4*)b)[t];
    float4 o;
    o.x = (xv.x - mu) * rstd * gv.x + bv.x;
    o.y = (xv.y - mu) * rstd * gv.y + bv.y;
    o.z = (xv.z - mu) * rstd * gv.z + bv.z;
    o.w = (xv.w - mu) * rstd * gv.w + bv.w;
    size_t idx = (size_t)row * ND + t * 4;
    *(float4*)(g_xn + idx) = o;
    *(__half2*)(g_xnh + idx)     = __floats2half2_rn(o.x, o.y);
    *(__half2*)(g_xnh + idx + 2) = __floats2half2_rn(o.z, o.w);
}

// ---------------- Softmax: fp32 scores -> fp16 probs ------------------------
__global__ __launch_bounds__(256) void softmax_kernel() {
    int row = blockIdx.x;
    int t = threadIdx.x;
    const float4* r = (const float4*)(g_s + (size_t)row * SQ);
    float4 v[4];
    float mx = -1e30f;
    #pragma unroll
    for (int i = 0; i < 4; i++) {
        v[i] = r[t + i * 256];
        mx = fmaxf(mx, fmaxf(fmaxf(v[i].x, v[i].y), fmaxf(v[i].z, v[i].w)));
    }
    __shared__ float shA[8], shB[8];
    mx = warpMax(mx);
    if ((t & 31) == 0) shA[t >> 5] = mx;
    __syncthreads();
    if (t < 32) {
        float a = (t < 8) ? shA[t] : -1e30f;
        a = warpMax(a);
        if (t == 0) shA[0] = a;
    }
    __syncthreads();
    mx = shA[0];

    float sum = 0.0f;
    #pragma unroll
    for (int i = 0; i < 4; i++) {
        v[i].x = __expf(v[i].x - mx);
        v[i].y = __expf(v[i].y - mx);
        v[i].z = __expf(v[i].z - mx);
        v[i].w = __expf(v[i].w - mx);
        sum += v[i].x + v[i].y + v[i].z + v[i].w;
    }
    sum = warpSum(sum);
    if ((t & 31) == 0) shB[t >> 5] = sum;
    __syncthreads();
    if (t < 32) {
        float a = (t < 8) ? shB[t] : 0.0f;
        a = warpSum(a);
        if (t == 0) shB[0] = a;
    }
    __syncthreads();
    float inv = 1.0f / shB[0];
    #pragma unroll
    for (int i = 0; i < 4; i++) {
        size_t idx = (size_t)row * SQ + (t + i * 256) * 4;
        *(__half2*)(g_p + idx)     = __floats2half2_rn(v[i].x * inv, v[i].y * inv);
        *(__half2*)(g_p + idx + 2) = __floats2half2_rn(v[i].z * inv, v[i].w * inv);
    }
}

// ---------------- fp16 tensor-core GEMM -------------------------------------
// C[M,Nn] = act(scale*(A @ B^T) + bias) (+resid)
// A [M,K] fp16 row-major, B [Nn,K] fp16 row-major.
// MODE 0: fp32 out Cf (+resid, scale). MODE 1: fp16 out Ch row-major (bias, act).
// MODE 2: fp16 out transposed Ch[col*M + row] (bias).
// Tile: 128x128, 4 warps (64x64 each), BK=32 halves, 3-stage cp.async,
// single __syncthreads per k-tile (loads issued after compute).
template<int MODE, int ACT, bool RES>
__global__ __launch_bounds__(128, 2) void hgemm_kernel(
    const __half* __restrict__ A, const __half* __restrict__ B,
    const float* __restrict__ bias, const float* __restrict__ resid,
    float* __restrict__ Cf, __half* __restrict__ Ch,
    int M, int Nn, int K, float scale)
{
    constexpr int BK = 32;          // k-chunk in halves
    constexpr int PITCH = 40;       // smem row pitch in halves (conflict-free)
    constexpr int TST = 128 * PITCH;   // halves per tile-stage (A or B)

    extern __shared__ __half smem[];
    __half* Asm = smem;                // [3][TST]
    __half* Bsm = smem + 3 * TST;      // [3][TST]

    int tid  = threadIdx.x;
    int wid  = tid >> 5;
    int lane = tid & 31;
    int grp  = lane >> 2;     // 0..7
    int tig  = lane & 3;      // 0..3
    int wm = (wid & 1) * 64;
    int wn = (wid >> 1) * 64;
    int bm = blockIdx.y * 128;
    int bn = blockIdx.x * 128;

    float acc[4][8][4];
    #pragma unroll
    for (int i = 0; i < 4; i++)
        #pragma unroll
        for (int j = 0; j < 8; j++)
            #pragma unroll
            for (int c = 0; c < 4; c++) acc[i][j][c] = 0.0f;

    // load one 128x32 tile pair (A and B) into stage s
    auto loadTile = [&](int s, int k0) {
        __half* As = Asm + s * TST;
        __half* Bs = Bsm + s * TST;
        #pragma unroll
        for (int it = 0; it < 4; it++) {
            int idx = tid + it * 128;     // 0..511
            int r = idx >> 2;             // 0..127
            int ch = (idx & 3) << 3;      // half-offset 0,8,16,24
            cp_async16(As + r * PITCH + ch, A + (size_t)(bm + r) * K + k0 + ch);
        }
        #pragma unroll
        for (int it = 0; it < 4; it++) {
            int idx = tid + it * 128;
            int r = idx >> 2;
            int ch = (idx & 3) << 3;
            cp_async16(Bs + r * PITCH + ch, B + (size_t)(bn + r) * K + k0 + ch);
        }
        cp_commit();
    };

    int nt = K / BK;
    loadTile(0, 0);
    loadTile(1, BK);

    int s = 0, sl = 2;
    for (int t = 0; t < nt; t++) {
        if (t + 1 < nt) cp_wait<1>(); else cp_wait<0>();
        __syncthreads();

        const __half* As = Asm + s * TST;
        const __half* Bs = Bsm + s * TST;

        #pragma unroll
        for (int ks = 0; ks < 2; ks++) {
            uint32_t af[4][4];
            uint32_t bf[8][2];
            #pragma unroll
            for (int mi = 0; mi < 4; mi++) {
                const __half* ap = &As[(wm + mi * 16 + grp) * PITCH + ks * 16 + tig * 2];
                af[mi][0] = *(const uint32_t*)(ap);                 // (g,    2t..2t+1)
                af[mi][1] = *(const uint32_t*)(ap + 8 * PITCH);     // (g+8,  2t..2t+1)
                af[mi][2] = *(const uint32_t*)(ap + 8);             // (g,    2t+8..9)
                af[mi][3] = *(const uint32_t*)(ap + 8 * PITCH + 8); // (g+8,  2t+8..9)
            }
            #pragma unroll
            for (int ni = 0; ni < 8; ni++) {
                const __half* bp = &Bs[(wn + ni * 8 + grp) * PITCH + ks * 16 + tig * 2];
                bf[ni][0] = *(const uint32_t*)(bp);                 // (n g, k 2t..2t+1)
                bf[ni][1] = *(const uint32_t*)(bp + 8);             // (n g, k 2t+8..9)
            }
            #pragma unroll
            for (int mi = 0; mi < 4; mi++)
                #pragma unroll
                for (int ni = 0; ni < 8; ni++)
                    mma_f16(acc[mi][ni], af[mi], bf[ni]);
        }

        if (t + 2 < nt) loadTile(sl, (t + 2) * BK);
        s  = (s  == 2) ? 0 : s + 1;
        sl = (sl == 2) ? 0 : sl + 1;
    }

    // epilogue: c0=(g,2t) c1=(g,2t+1) c2=(g+8,2t) c3=(g+8,2t+1)
    #pragma unroll
    for (int mi = 0; mi < 4; mi++) {
        #pragma unroll
        for (int ni = 0; ni < 8; ni++) {
            int col = bn + wn + ni * 8 + 2 * tig;
            float b0v = bias ? bias[col]     : 0.0f;
            float b1v = bias ? bias[col + 1] : 0.0f;
            #pragma unroll
            for (int rr = 0; rr < 2; rr++) {
                int row = bm + wm + mi * 16 + grp + rr * 8;
                float v0 = acc[mi][ni][rr * 2 + 0] * scale + b0v;
                float v1 = acc[mi][ni][rr * 2 + 1] * scale + b1v;
                if (ACT == 1) {
                    v0 = (v0 > 0.0f) ? v0 : 0.1f * v0;
                    v1 = (v1 > 0.0f) ? v1 : 0.1f * v1;
                }
                if (MODE == 0) {
                    size_t off = (size_t)row * Nn + col;
                    if (RES) { v0 += resid[off]; v1 += resid[off + 1]; }
                    *(float2*)(Cf + off) = make_float2(v0, v1);
                } else if (MODE == 1) {
                    size_t off = (size_t)row * Nn + col;
                    *(__half2*)(Ch + off) = __floats2half2_rn(v0, v1);
                } else {
                    Ch[(size_t)col * M + row]       = __float2half_rn(v0);
                    Ch[(size_t)(col + 1) * M + row] = __float2half_rn(v1);
                }
            }
        }
    }
}

static constexpr int SMEM_H = 6 * 128 * 40 * 2;   // 61440 bytes

// ---------------- host side ----------------
extern "C" void kernel_launch(void* const* d_in, const int* in_sizes, int n_in,
                              void* d_out, int out_size) {
    const float* x      = (const float*)d_in[0];
    const float* norm_g = (const float*)d_in[1];
    const float* norm_b = (const float*)d_in[2];
    const float* Wq = (const float*)d_in[3];
    const float* bq = (const float*)d_in[4];
    const float* Wk = (const float*)d_in[5];
    const float* bk = (const float*)d_in[6];
    const float* Wv = (const float*)d_in[7];
    const float* bv = (const float*)d_in[8];
    const float* W1 = (const float*)d_in[9];
    const float* b1 = (const float*)d_in[10];
    const float* W2 = (const float*)d_in[11];
    const float* b2 = (const float*)d_in[12];
    float* out = (float*)d_out;

    float  *xn, *s;
    __half *xnh, *qh, *kh, *vT, *p, *h, *mid;
    __half *wqT, *wkT, *wvT, *w1T, *w2T;
    cudaGetSymbolAddress((void**)&xn,  g_xn);
    cudaGetSymbolAddress((void**)&s,   g_s);
    cudaGetSymbolAddress((void**)&xnh, g_xnh);
    cudaGetSymbolAddress((void**)&qh,  g_qh);
    cudaGetSymbolAddress((void**)&kh,  g_kh);
    cudaGetSymbolAddress((void**)&vT,  g_vT);
    cudaGetSymbolAddress((void**)&p,   g_p);
    cudaGetSymbolAddress((void**)&h,   g_h);
    cudaGetSymbolAddress((void**)&mid, g_mid);
    cudaGetSymbolAddress((void**)&wqT, g_wqT);
    cudaGetSymbolAddress((void**)&wkT, g_wkT);
    cudaGetSymbolAddress((void**)&wvT, g_wvT);
    cudaGetSymbolAddress((void**)&w1T, g_w1T);
    cudaGetSymbolAddress((void**)&w2T, g_w2T);

    cudaFuncSetAttribute(hgemm_kernel<0,0,false>, cudaFuncAttributeMaxDynamicSharedMemorySize, SMEM_H);
    cudaFuncSetAttribute(hgemm_kernel<0,0,true >, cudaFuncAttributeMaxDynamicSharedMemorySize, SMEM_H);
    cudaFuncSetAttribute(hgemm_kernel<1,0,false>, cudaFuncAttributeMaxDynamicSharedMemorySize, SMEM_H);
    cudaFuncSetAttribute(hgemm_kernel<1,1,false>, cudaFuncAttributeMaxDynamicSharedMemorySize, SMEM_H);
    cudaFuncSetAttribute(hgemm_kernel<2,0,false>, cudaFuncAttributeMaxDynamicSharedMemorySize, SMEM_H);

    // 0. weight prep (transpose + fp16)
    wprep_kernel<<<dim3(ND/32, ND/32), 256>>>(Wq, wqT, ND, ND);
    wprep_kernel<<<dim3(ND/32, ND/32), 256>>>(Wk, wkT, ND, ND);
    wprep_kernel<<<dim3(ND/32, ND/32), 256>>>(Wv, wvT, ND, ND);
    wprep_kernel<<<dim3(FD/32, ND/32), 256>>>(W1, w1T, ND, FD);
    wprep_kernel<<<dim3(ND/32, FD/32), 256>>>(W2, w2T, FD, ND);

    // 1. LayerNorm
    ln_kernel<<<SQ, 256>>>(x, norm_g, norm_b);

    // 2. q/k/v projections  (C = xn @ WT^T), v written transposed
    dim3 gNN(ND/128, SQ/128);           // (8, 32)
    hgemm_kernel<1,0,false><<<gNN, 128, SMEM_H>>>(xnh, wqT, bq, nullptr, nullptr, qh, SQ, ND, ND, 1.0f);
    hgemm_kernel<1,0,false><<<gNN, 128, SMEM_H>>>(xnh, wkT, bk, nullptr, nullptr, kh, SQ, ND, ND, 1.0f);
    hgemm_kernel<2,0,false><<<gNN, 128, SMEM_H>>>(xnh, wvT, bv, nullptr, nullptr, vT, SQ, ND, ND, 1.0f);

    // 3. scores = (k @ q^T)/sqrt(N)  -> fp32 [SQ,SQ]
    dim3 gSS(SQ/128, SQ/128);           // (32, 32)
    hgemm_kernel<0,0,false><<<gSS, 128, SMEM_H>>>(kh, qh, nullptr, nullptr, s, nullptr, SQ, SQ, ND, 0.03125f);

    // 4. softmax -> fp16 probs
    softmax_kernel<<<SQ, 256>>>();

    // 5. h = P @ v   (B = v^T [ND][SQ])
    hgemm_kernel<1,0,false><<<gNN, 128, SMEM_H>>>(p, vT, nullptr, nullptr, nullptr, h, SQ, ND, SQ, 1.0f);

    // 6. mid = leaky_relu(h @ W1 + b1)
    dim3 gNF(FD/128, SQ/128);           // (32, 32)
    hgemm_kernel<1,1,false><<<gNF, 128, SMEM_H>>>(h, w1T, b1, nullptr, nullptr, mid, SQ, FD, ND, 1.0f);

    // 7. out = mid @ W2 + b2 + xn
    hgemm_kernel<0,0,true><<<gNN, 128, SMEM_H>>>(mid, w2T, b2, xn, out, nullptr, SQ, ND, FD, 1.0f);
}